// round 17
// baseline (speedup 1.0000x reference)
#include <cuda_runtime.h>
#include <cuda_bf16.h>

// out[b] = sum_k x[b,k] * |W[k]| * fc1_w[k] + fc1_b
// B=32, K = T*P = 4,000,000
#define NBATCH  32
#define TP      4000000
#define NVEC8   (TP / 8)      // 500,000 float8 per batch row
#define GROUPS  27            // grid 864 ~= 148 SM * 6 CTA (proven optimum)
#define THREADS 256
#define STRIDE8 (GROUPS * THREADS)   // 6912 float8 per sweep

__global__ void init_out_kernel(const float* __restrict__ fc1_b,
                                float* __restrict__ out) {
    out[threadIdx.x] = fc1_b[0];
}

// 256-bit global loads (sm_100+). 32B-aligned: all offsets are float8 units.
__device__ __forceinline__ void ldg8_cs(const float* p, float* r) {
    asm volatile("ld.global.cs.v8.f32 {%0,%1,%2,%3,%4,%5,%6,%7}, [%8];"
                 : "=f"(r[0]), "=f"(r[1]), "=f"(r[2]), "=f"(r[3]),
                   "=f"(r[4]), "=f"(r[5]), "=f"(r[6]), "=f"(r[7])
                 : "l"(p));
}
__device__ __forceinline__ void ldg8_nc(const float* p, float* r) {
    asm volatile("ld.global.nc.v8.f32 {%0,%1,%2,%3,%4,%5,%6,%7}, [%8];"
                 : "=f"(r[0]), "=f"(r[1]), "=f"(r[2]), "=f"(r[3]),
                   "=f"(r[4]), "=f"(r[5]), "=f"(r[6]), "=f"(r[7])
                 : "l"(p));
}

__global__ __launch_bounds__(THREADS, 6)   // 6 CTAs/SM: proven optimum
void dot_kernel(const float* __restrict__ x,
                const float* __restrict__ W,
                const float* __restrict__ F,
                float* __restrict__ out) {
    const int b   = blockIdx.x & (NBATCH - 1);   // batch (fastest-varying)
    const int g   = blockIdx.x >> 5;             // column group 0..26
    const int tid = threadIdx.x;

    const float* __restrict__ xb = x + (size_t)b * TP;

    float a0 = 0.f, a1 = 0.f, a2 = 0.f, a3 = 0.f;

#pragma unroll 1
    for (int j = g * THREADS + tid; j < NVEC8; j += STRIDE8) {
        const size_t e0 = (size_t)j * 8;
        float xr[8], wr[8], fr[8];
        // x: read-once stream -> evict-first (proven); 1024B/warp/instr
        ldg8_cs(xb + e0, xr);
        // W/F: L2-shared across the 32 co-resident batch-blocks
        ldg8_nc(W + e0, wr);
        ldg8_nc(F + e0, fr);
        a0 = fmaf(xr[0], fabsf(wr[0]) * fr[0], a0);
        a1 = fmaf(xr[1], fabsf(wr[1]) * fr[1], a1);
        a2 = fmaf(xr[2], fabsf(wr[2]) * fr[2], a2);
        a3 = fmaf(xr[3], fabsf(wr[3]) * fr[3], a3);
        a0 = fmaf(xr[4], fabsf(wr[4]) * fr[4], a0);
        a1 = fmaf(xr[5], fabsf(wr[5]) * fr[5], a1);
        a2 = fmaf(xr[6], fabsf(wr[6]) * fr[6], a2);
        a3 = fmaf(xr[7], fabsf(wr[7]) * fr[7], a3);
    }

    float v = (a0 + a1) + (a2 + a3);

    // ---- block reduction: warp shfl -> smem -> single atomic ----
    __shared__ float sred[THREADS / 32];
    const int lane = tid & 31;
    const int wrp  = tid >> 5;

#pragma unroll
    for (int off = 16; off; off >>= 1)
        v += __shfl_xor_sync(0xffffffffu, v, off);
    if (lane == 0) sred[wrp] = v;
    __syncthreads();

    if (wrp == 0) {
        float s = (lane < THREADS / 32) ? sred[lane] : 0.f;
#pragma unroll
        for (int off = 4; off; off >>= 1)
            s += __shfl_xor_sync(0xffffffffu, s, off);
        if (lane == 0) atomicAdd(&out[b], s);
    }
}

extern "C" void kernel_launch(void* const* d_in, const int* in_sizes, int n_in,
                              void* d_out, int out_size) {
    const float* x  = (const float*)d_in[0];  // [32, 4M]
    const float* W  = (const float*)d_in[1];  // [4M]
    const float* F  = (const float*)d_in[2];  // fc1_w [4M]
    const float* bb = (const float*)d_in[3];  // fc1_b [1]
    float* out = (float*)d_out;               // [32]

    (void)in_sizes; (void)n_in; (void)out_size;

    init_out_kernel<<<1, NBATCH>>>(bb, out);
    dot_kernel<<<NBATCH * GROUPS, THREADS>>>(x, W, F, out);
}